// round 7
// baseline (speedup 1.0000x reference)
#include <cuda_runtime.h>

// Involution: B=4, H=W=56, C=256, Cr=64, G=16, Cg=16, K=7, pad=3
// Round 6: 8x8 tiles, f32x2 packed FMA in span-GEMM (rs stored transposed,
// pixel-pair ld.shared.b64), channel-major conflict-free halo, column B4,
// prep transpose folded into rs_kernel.

#define HH 56
#define WWD 56
#define CC 256
#define CR 64
#define NG 16
#define CGC 16
#define KKT 49
#define NPIXT 12544
#define TILE 8
#define HALO 14          // TILE + 6
#define NPOS 196         // 14*14
#define XHU 202          // padded pos count (202 mod 8 == 2 -> bank-clean)
#define KGP 52
#define RSPAD 66

using u64 = unsigned long long;

__device__ __align__(16) float g_wsT[NG * KKT * CR];   // [g*49+k][d]
__device__ __align__(16) float g_rs[(size_t)NPIXT * CR];

__device__ __forceinline__ u64 pack2(float lo, float hi) {
    u64 r; asm("mov.b64 %0,{%1,%2};" : "=l"(r) : "f"(lo), "f"(hi)); return r;
}
__device__ __forceinline__ u64 fma2(u64 a, u64 b, u64 c) {
    u64 d; asm("fma.rn.f32x2 %0,%1,%2,%3;" : "=l"(d) : "l"(a), "l"(b), "l"(c)); return d;
}
__device__ __forceinline__ void unpack2(u64 v, float& lo, float& hi) {
    asm("mov.b64 {%0,%1},%2;" : "=f"(lo), "=f"(hi) : "l"(v));
}
__device__ __forceinline__ u64 lds64(unsigned a) {
    u64 v; asm("ld.shared.b64 %0,[%1];" : "=l"(v) : "r"(a)); return v;
}

// ---------------------------------------------------------------- rs GEMM + w_span transpose
#define RPX 128
struct SmemR {
    float xs[RPX][68];
    float ws[CR][CR];
};

__global__ __launch_bounds__(256)
void rs_kernel(const float* __restrict__ x,
               const float* __restrict__ wr,
               const float* __restrict__ gamma,
               const float* __restrict__ beta,
               const float* __restrict__ mean,
               const float* __restrict__ var,
               const float* __restrict__ wspan) {
    extern __shared__ __align__(16) float smr[];
    SmemR& s = *reinterpret_cast<SmemR*>(smr);
    __shared__ float ttile[32][33];
    const int t = threadIdx.x;

    // folded prep: transpose w_span into g_wsT (blocks 0..49)
    if (blockIdx.x < 50) {
        const int tx = t & 31, ty8 = t >> 5;
        const int gk0 = (blockIdx.x % 25) * 32, d0v = (blockIdx.x / 25) * 32;
        #pragma unroll
        for (int r = 0; r < 32; r += 8) {
            int d = d0v + ty8 + r, gk = gk0 + tx;
            ttile[ty8 + r][tx] = (gk < KKT * NG) ? wspan[(size_t)d * (KKT * NG) + gk] : 0.f;
        }
        __syncthreads();
        #pragma unroll
        for (int r = 0; r < 32; r += 8) {
            int gk = gk0 + ty8 + r, d = d0v + tx;
            if (gk < KKT * NG) g_wsT[(size_t)gk * CR + d] = ttile[tx][ty8 + r];
        }
        __syncthreads();
    }

    const int pix0 = blockIdx.x * RPX;
    const int dt = t & 15, mt = t >> 4;
    const int d0 = dt * 4;

    float4 acc[8];
    #pragma unroll
    for (int i = 0; i < 8; ++i) acc[i] = make_float4(0.f, 0.f, 0.f, 0.f);

    for (int cb = 0; cb < 4; ++cb) {
        for (int i = t; i < RPX * 16; i += 256) {
            int p = i >> 4, c = i & 15;
            *(float4*)&s.xs[p][c * 4] =
                __ldg((const float4*)&x[(size_t)(pix0 + p) * CC + cb * 64 + c * 4]);
        }
        for (int i = t; i < 64 * 16; i += 256) {
            int r = i >> 4, c = i & 15;
            *(float4*)&s.ws[r][c * 4] =
                __ldg((const float4*)&wr[(size_t)(cb * 64 + r) * CR + c * 4]);
        }
        __syncthreads();
        #pragma unroll 4
        for (int c4 = 0; c4 < 16; ++c4) {
            float4 w0 = *(float4*)&s.ws[c4 * 4 + 0][d0];
            float4 w1 = *(float4*)&s.ws[c4 * 4 + 1][d0];
            float4 w2 = *(float4*)&s.ws[c4 * 4 + 2][d0];
            float4 w3 = *(float4*)&s.ws[c4 * 4 + 3][d0];
            #pragma unroll
            for (int i = 0; i < 8; ++i) {
                float4 a = *(float4*)&s.xs[mt * 8 + i][c4 * 4];
                acc[i].x += a.x*w0.x + a.y*w1.x + a.z*w2.x + a.w*w3.x;
                acc[i].y += a.x*w0.y + a.y*w1.y + a.z*w2.y + a.w*w3.y;
                acc[i].z += a.x*w0.z + a.y*w1.z + a.z*w2.z + a.w*w3.z;
                acc[i].w += a.x*w0.w + a.y*w1.w + a.z*w2.w + a.w*w3.w;
            }
        }
        __syncthreads();
    }
    float4 gm = __ldg((const float4*)&gamma[d0]);
    float4 bt = __ldg((const float4*)&beta[d0]);
    float4 mn = __ldg((const float4*)&mean[d0]);
    float4 vr = __ldg((const float4*)&var[d0]);
    float4 sc, bb2;
    sc.x = gm.x * rsqrtf(vr.x + 1e-3f); bb2.x = bt.x - mn.x * sc.x;
    sc.y = gm.y * rsqrtf(vr.y + 1e-3f); bb2.y = bt.y - mn.y * sc.y;
    sc.z = gm.z * rsqrtf(vr.z + 1e-3f); bb2.z = bt.z - mn.z * sc.z;
    sc.w = gm.w * rsqrtf(vr.w + 1e-3f); bb2.w = bt.w - mn.w * sc.w;
    #pragma unroll
    for (int i = 0; i < 8; ++i) {
        float4 v;
        v.x = fmaxf(acc[i].x * sc.x + bb2.x, 0.f);
        v.y = fmaxf(acc[i].y * sc.y + bb2.y, 0.f);
        v.z = fmaxf(acc[i].z * sc.z + bb2.z, 0.f);
        v.w = fmaxf(acc[i].w * sc.w + bb2.w, 0.f);
        *(float4*)&g_rs[(size_t)(pix0 + mt * 8 + i) * CR + d0] = v;
    }
}

// ---------------------------------------------------------------- main
struct SmemM {
    float  rsP[CR][RSPAD];        // 16896 B  rs transposed: [d][px]
    float4 xh4[2][2][4][XHU];     // 51712 B  halo, channel-major, double-buffered
    float  kg[2][64][KGP];        // 26624 B  kernels [g][px][k]
};                                // 95232 B

__device__ __forceinline__ void halo_load(SmemM& s, const float* __restrict__ x,
                                          int gA, int buf, int tl, int nthr,
                                          int h0, int w0, int bb) {
    for (int i = tl; i < 2 * NPOS * 4; i += nthr) {
        int g = i / (NPOS * 4);
        int rem = i - g * (NPOS * 4);
        int pos = rem >> 2, q = rem & 3;
        int hh = pos / HALO, ww = pos - hh * HALO;
        int h = h0 + hh - 3, w = w0 + ww - 3;
        float4 v = make_float4(0.f, 0.f, 0.f, 0.f);
        if (h >= 0 && h < HH && w >= 0 && w < WWD)
            v = __ldg((const float4*)&x[(((size_t)bb * HH + h) * WWD + w) * CC
                                        + (gA + g) * CGC + q * 4]);
        s.xh4[buf][g][q][pos] = v;
    }
}

__global__ __launch_bounds__(256, 2)
void inv_main(const float* __restrict__ x,
              const float* __restrict__ b_span,
              float* __restrict__ out) {
    extern __shared__ __align__(16) float smf[];
    SmemM& s = *reinterpret_cast<SmemM*>(smf);
    const int t = threadIdx.x;
    const int w0 = blockIdx.x * TILE, h0 = blockIdx.y * TILE;
    const int bb = blockIdx.z >> 1, ghalf = blockIdx.z & 1;
    const size_t pixbase = ((size_t)bb * HH + h0) * WWD + w0;

    // stage rs transposed: rsP[d][px]
    for (int i = t; i < 64 * 16; i += 256) {
        int px = i >> 4, c = i & 15;
        int py = px >> 3, pxl = px & 7;
        size_t pix = pixbase + (size_t)py * WWD + pxl;
        float4 v = __ldg((const float4*)&g_rs[pix * CR + c * 4]);
        s.rsP[c * 4 + 0][px] = v.x;
        s.rsP[c * 4 + 1][px] = v.y;
        s.rsP[c * 4 + 2][px] = v.z;
        s.rsP[c * 4 + 3][px] = v.w;
    }
    halo_load(s, x, ghalf * 8, 0, t, 256, h0, w0, bb);
    __syncthreads();

    const unsigned rs_base = (unsigned)__cvta_generic_to_shared(&s.rsP[0][0]);

    for (int gpl = 0; gpl < 4; ++gpl) {
        const int gp = ghalf * 4 + gpl;
        const int gA = gp * 2;
        const int buf = gpl & 1;

        if (t < 128) {
            if (t < 112) {
                // B3: kg[px][k] = rs . wsT + bias, f32x2 over pixel pairs
                const int g = t / 56, r = t - g * 56;
                const int quad = r & 7, kgi = r >> 3;   // kgi 0..6
                const int k0 = kgi * 7;
                const float* wrow = g_wsT + (size_t)((gA + g) * KKT + k0) * CR;
                const float* bs = b_span + (gA + g) * KKT + k0;
                u64 acc2[4][7];
                #pragma unroll
                for (int j = 0; j < 7; ++j) {
                    float bv = __ldg(&bs[j]);
                    u64 b2 = pack2(bv, bv);
                    acc2[0][j] = b2; acc2[1][j] = b2; acc2[2][j] = b2; acc2[3][j] = b2;
                }
                const unsigned co0 = (2 * (quad +  0)) * 4u;
                const unsigned co1 = (2 * (quad +  8)) * 4u;
                const unsigned co2 = (2 * (quad + 16)) * 4u;
                const unsigned co3 = (2 * (quad + 24)) * 4u;
                #pragma unroll 2
                for (int d4 = 0; d4 < 16; ++d4) {
                    float4 wv[7];
                    #pragma unroll
                    for (int j = 0; j < 7; ++j)
                        wv[j] = __ldg((const float4*)&wrow[j * CR + d4 * 4]);
                    #pragma unroll
                    for (int dd = 0; dd < 4; ++dd) {
                        unsigned rowa = rs_base + (unsigned)((d4 * 4 + dd) * RSPAD) * 4u;
                        u64 rp0 = lds64(rowa + co0);
                        u64 rp1 = lds64(rowa + co1);
                        u64 rp2 = lds64(rowa + co2);
                        u64 rp3 = lds64(rowa + co3);
                        #pragma unroll
                        for (int j = 0; j < 7; ++j) {
                            float w = (dd == 0) ? wv[j].x : (dd == 1) ? wv[j].y
                                    : (dd == 2) ? wv[j].z : wv[j].w;
                            u64 w2 = pack2(w, w);
                            acc2[0][j] = fma2(rp0, w2, acc2[0][j]);
                            acc2[1][j] = fma2(rp1, w2, acc2[1][j]);
                            acc2[2][j] = fma2(rp2, w2, acc2[2][j]);
                            acc2[3][j] = fma2(rp3, w2, acc2[3][j]);
                        }
                    }
                }
                #pragma unroll
                for (int i = 0; i < 4; ++i) {
                    int px = 2 * (quad + 8 * i);
                    #pragma unroll
                    for (int j = 0; j < 7; ++j) {
                        float lo, hi;
                        unpack2(acc2[i][j], lo, hi);
                        s.kg[g][px][k0 + j] = lo;
                        s.kg[g][px + 1][k0 + j] = hi;
                    }
                }
            }
            // t in [112,128): idle during B3 (keeps warp 3 convergent for B3 half)
        } else if (gpl < 3) {
            halo_load(s, x, gA + 2, buf ^ 1, t - 128, 128, h0, w0, bb);
        }
        __syncthreads();

        if (t < 128) {
            // B4: 4-px column per thread, 7-wide sliding window, channel-major halo
            const int g = t >> 6, r = t & 63;
            const int hhalf = r >> 5, rr2 = r & 31;
            const int pxl = rr2 >> 2, c4 = rr2 & 3;
            const int pybase = hhalf * 4;
            float4 acc[4];
            acc[0] = acc[1] = acc[2] = acc[3] = make_float4(0.f, 0.f, 0.f, 0.f);
            const float4* xcol = &s.xh4[buf][g][c4][0];
            #pragma unroll
            for (int rr = 0; rr < 10; ++rr) {
                const int row = pybase + rr;
                float4 xw[7];
                #pragma unroll
                for (int kw = 0; kw < 7; ++kw)
                    xw[kw] = xcol[row * HALO + pxl + kw];
                #pragma unroll
                for (int py = 0; py < 4; ++py) {
                    if (py <= rr && rr - py <= 6) {
                        const int kh = rr - py;
                        const float* kgr = &s.kg[g][(pybase + py) * 8 + pxl][kh * 7];
                        #pragma unroll
                        for (int kw = 0; kw < 7; ++kw) {
                            float kv = kgr[kw];
                            acc[py].x += kv * xw[kw].x;
                            acc[py].y += kv * xw[kw].y;
                            acc[py].z += kv * xw[kw].z;
                            acc[py].w += kv * xw[kw].w;
                        }
                    }
                }
            }
            #pragma unroll
            for (int py = 0; py < 4; ++py) {
                size_t o = (pixbase + (size_t)(pybase + py) * WWD + pxl) * CC
                         + (gA + g) * CGC + c4 * 4;
                *(float4*)&out[o] = acc[py];
            }
        }
        __syncthreads();
    }
}

// ---------------------------------------------------------------- launch
extern "C" void kernel_launch(void* const* d_in, const int* in_sizes, int n_in,
                              void* d_out, int out_size) {
    (void)in_sizes; (void)n_in; (void)out_size;
    const float* x        = (const float*)d_in[0];
    const float* w_reduce = (const float*)d_in[1];
    const float* gamma    = (const float*)d_in[2];
    const float* beta     = (const float*)d_in[3];
    const float* mean     = (const float*)d_in[4];
    const float* var      = (const float*)d_in[5];
    const float* w_span   = (const float*)d_in[6];
    const float* b_span   = (const float*)d_in[7];
    float* out = (float*)d_out;

    cudaFuncSetAttribute(rs_kernel, cudaFuncAttributeMaxDynamicSharedMemorySize,
                         (int)sizeof(SmemR));
    cudaFuncSetAttribute(inv_main, cudaFuncAttributeMaxDynamicSharedMemorySize,
                         (int)sizeof(SmemM));

    rs_kernel<<<NPIXT / RPX, 256, sizeof(SmemR)>>>(x, w_reduce, gamma, beta,
                                                   mean, var, w_span);
    dim3 grid(WWD / TILE, HH / TILE, 8);   // (7, 7, 8) = 392 CTAs
    inv_main<<<grid, 256, sizeof(SmemM)>>>(x, b_span, out);
}

// round 8
// speedup vs baseline: 1.3384x; 1.3384x over previous
#include <cuda_runtime.h>

// Involution: B=4, H=W=56, C=256, Cr=64, G=16, Cg=16, K=7, pad=3
// Round 7: all-threads-active phases, 3 CTAs/SM (68KB smem, <=84 regs),
// quarter-warp-clean smem layouts, transpose overlapped with rs GEMM.

#define HH 56
#define WWD 56
#define CC 256
#define CR 64
#define NG 16
#define CGC 16
#define KKT 49
#define NPIXT 12544
#define TILE 8
#define HALO 14
#define NPOS 196         // 14*14
#define KGP 50
#define RSPD 68

__device__ __align__(16) float g_wsT[NG * KKT * CR];   // [g*49+k][d]
__device__ __align__(16) float g_rs[(size_t)NPIXT * CR];

// ------------------------------------------------ rs GEMM (+ overlapped w_span transpose)
#define RPX 128
#define NRSBLK 98        // GEMM blocks; blocks [98,148) transpose w_span
struct SmemR {
    float xs[RPX][68];
    float ws[CR][CR];
};

__global__ __launch_bounds__(256)
void rs_kernel(const float* __restrict__ x,
               const float* __restrict__ wr,
               const float* __restrict__ gamma,
               const float* __restrict__ beta,
               const float* __restrict__ mean,
               const float* __restrict__ var,
               const float* __restrict__ wspan) {
    extern __shared__ __align__(16) float smr[];
    SmemR& s = *reinterpret_cast<SmemR*>(smr);
    const int t = threadIdx.x;

    if (blockIdx.x >= NRSBLK) {
        // transpose-only block: 32x32 tile of w_span -> g_wsT
        __shared__ float ttile[32][33];
        const int bt = blockIdx.x - NRSBLK;          // 0..49
        const int tx = t & 31, ty8 = t >> 5;
        const int gk0 = (bt % 25) * 32, d0v = (bt / 25) * 32;
        #pragma unroll
        for (int r = 0; r < 32; r += 8) {
            int d = d0v + ty8 + r, gk = gk0 + tx;
            ttile[ty8 + r][tx] = (gk < KKT * NG) ? wspan[(size_t)d * (KKT * NG) + gk] : 0.f;
        }
        __syncthreads();
        #pragma unroll
        for (int r = 0; r < 32; r += 8) {
            int gk = gk0 + ty8 + r, d = d0v + tx;
            if (gk < KKT * NG) g_wsT[(size_t)gk * CR + d] = ttile[tx][ty8 + r];
        }
        return;
    }

    const int pix0 = blockIdx.x * RPX;
    const int dt = t & 15, mt = t >> 4;
    const int d0 = dt * 4;

    float4 acc[8];
    #pragma unroll
    for (int i = 0; i < 8; ++i) acc[i] = make_float4(0.f, 0.f, 0.f, 0.f);

    for (int cb = 0; cb < 4; ++cb) {
        for (int i = t; i < RPX * 16; i += 256) {
            int p = i >> 4, c = i & 15;
            *(float4*)&s.xs[p][c * 4] =
                __ldg((const float4*)&x[(size_t)(pix0 + p) * CC + cb * 64 + c * 4]);
        }
        for (int i = t; i < 64 * 16; i += 256) {
            int r = i >> 4, c = i & 15;
            *(float4*)&s.ws[r][c * 4] =
                __ldg((const float4*)&wr[(size_t)(cb * 64 + r) * CR + c * 4]);
        }
        __syncthreads();
        #pragma unroll 4
        for (int c4 = 0; c4 < 16; ++c4) {
            float4 w0 = *(float4*)&s.ws[c4 * 4 + 0][d0];
            float4 w1 = *(float4*)&s.ws[c4 * 4 + 1][d0];
            float4 w2 = *(float4*)&s.ws[c4 * 4 + 2][d0];
            float4 w3 = *(float4*)&s.ws[c4 * 4 + 3][d0];
            #pragma unroll
            for (int i = 0; i < 8; ++i) {
                float4 a = *(float4*)&s.xs[mt * 8 + i][c4 * 4];
                acc[i].x += a.x*w0.x + a.y*w1.x + a.z*w2.x + a.w*w3.x;
                acc[i].y += a.x*w0.y + a.y*w1.y + a.z*w2.y + a.w*w3.y;
                acc[i].z += a.x*w0.z + a.y*w1.z + a.z*w2.z + a.w*w3.z;
                acc[i].w += a.x*w0.w + a.y*w1.w + a.z*w2.w + a.w*w3.w;
            }
        }
        __syncthreads();
    }
    float4 gm = __ldg((const float4*)&gamma[d0]);
    float4 bt4 = __ldg((const float4*)&beta[d0]);
    float4 mn = __ldg((const float4*)&mean[d0]);
    float4 vr = __ldg((const float4*)&var[d0]);
    float4 sc, bb2;
    sc.x = gm.x * rsqrtf(vr.x + 1e-3f); bb2.x = bt4.x - mn.x * sc.x;
    sc.y = gm.y * rsqrtf(vr.y + 1e-3f); bb2.y = bt4.y - mn.y * sc.y;
    sc.z = gm.z * rsqrtf(vr.z + 1e-3f); bb2.z = bt4.z - mn.z * sc.z;
    sc.w = gm.w * rsqrtf(vr.w + 1e-3f); bb2.w = bt4.w - mn.w * sc.w;
    #pragma unroll
    for (int i = 0; i < 8; ++i) {
        float4 v;
        v.x = fmaxf(acc[i].x * sc.x + bb2.x, 0.f);
        v.y = fmaxf(acc[i].y * sc.y + bb2.y, 0.f);
        v.z = fmaxf(acc[i].z * sc.z + bb2.z, 0.f);
        v.w = fmaxf(acc[i].w * sc.w + bb2.w, 0.f);
        *(float4*)&g_rs[(size_t)(pix0 + mt * 8 + i) * CR + d0] = v;
    }
}

// ------------------------------------------------ main
struct SmemM {
    float  rs[64][RSPD];          // 17408 B  [px][d]
    float4 xh4[2][4][NPOS];       // 25088 B  halo, [g][c4][pos], single buffer
    float  kg[2][64][KGP];        // 25600 B  [g][px][k]
};                                // 68096 B -> 3 CTAs/SM

__global__ __launch_bounds__(256, 3)
void inv_main(const float* __restrict__ x,
              const float* __restrict__ b_span,
              float* __restrict__ out) {
    extern __shared__ __align__(16) float smf[];
    SmemM& s = *reinterpret_cast<SmemM*>(smf);
    const int t = threadIdx.x;
    const int w0 = blockIdx.x * TILE, h0 = blockIdx.y * TILE;
    const int bb = blockIdx.z >> 1, ghalf = blockIdx.z & 1;
    const size_t pixbase = ((size_t)bb * HH + h0) * WWD + w0;

    // prologue: stage rs tile [64 px][64 d]
    for (int i = t; i < 64 * 16; i += 256) {
        int px = i >> 4, c = i & 15;
        int py = px >> 3, pxl = px & 7;
        size_t pix = pixbase + (size_t)py * WWD + pxl;
        *(float4*)&s.rs[px][c * 4] = __ldg((const float4*)&g_rs[pix * CR + c * 4]);
    }
    __syncthreads();

    for (int it = 0; it < 4; ++it) {
        const int gA = ghalf * 8 + it * 2;

        // ---- phase 1: halo load (all threads, LDG hidden behind B3 FMA) ----
        for (int i = t; i < 2 * NPOS * 4; i += 256) {
            int g = i >> 9;                  // i / 784... use exact: NPOS*4 = 784
            int rem = i - g * 784;
            if (i >= 784) { g = 1; rem = i - 784; } else { g = 0; rem = i; }
            int pos = rem >> 2, q = rem & 3;
            int hh = pos / HALO, ww = pos - hh * HALO;
            int h = h0 + hh - 3, w = w0 + ww - 3;
            float4 v = make_float4(0.f, 0.f, 0.f, 0.f);
            if (h >= 0 && h < HH && w >= 0 && w < WWD)
                v = __ldg((const float4*)&x[(((size_t)bb * HH + h) * WWD + w) * CC
                                            + (gA + g) * CGC + q * 4]);
            s.xh4[g][q][pos] = v;
        }

        // ---- B3: kg[g][px][k] = rs[px][:] . wsT[g][k][:] + bias (224 thr) ----
        if (t < 224) {
            const int g = t / 112, r = t - g * 112;
            const int quad = r & 15, kgi = r >> 4;   // 16 quads x 7 k-groups
            const int k0 = kgi * 7;
            const float* wrow = g_wsT + (size_t)((gA + g) * KKT + k0) * CR;
            const float* bs = b_span + (gA + g) * KKT + k0;
            float acc[4][7];
            #pragma unroll
            for (int j = 0; j < 7; ++j) {
                float bv = __ldg(&bs[j]);
                acc[0][j] = bv; acc[1][j] = bv; acc[2][j] = bv; acc[3][j] = bv;
            }
            #pragma unroll 4
            for (int d4 = 0; d4 < 16; ++d4) {
                float4 r0 = *(float4*)&s.rs[quad +  0][d4 * 4];
                float4 r1 = *(float4*)&s.rs[quad + 16][d4 * 4];
                float4 r2 = *(float4*)&s.rs[quad + 32][d4 * 4];
                float4 r3 = *(float4*)&s.rs[quad + 48][d4 * 4];
                #pragma unroll
                for (int j = 0; j < 7; ++j) {
                    float4 w4 = __ldg((const float4*)&wrow[j * CR + d4 * 4]);
                    acc[0][j] += r0.x*w4.x + r0.y*w4.y + r0.z*w4.z + r0.w*w4.w;
                    acc[1][j] += r1.x*w4.x + r1.y*w4.y + r1.z*w4.z + r1.w*w4.w;
                    acc[2][j] += r2.x*w4.x + r2.y*w4.y + r2.z*w4.z + r2.w*w4.w;
                    acc[3][j] += r3.x*w4.x + r3.y*w4.y + r3.z*w4.z + r3.w*w4.w;
                }
            }
            #pragma unroll
            for (int i = 0; i < 4; ++i)
                #pragma unroll
                for (int j = 0; j < 7; ++j)
                    s.kg[g][quad + 16 * i][k0 + j] = acc[i][j];
        }
        __syncthreads();

        // ---- B4: 2-px column per thread, 8-row sliding window (256 thr) ----
        {
            const int g = t >> 7, r = t & 127;
            const int pyq = r >> 5, rr = r & 31;
            const int c4 = rr >> 3, pxl = rr & 7;   // quarter-warp: same c4, pxl 0-7
            const int py0 = pyq * 2;
            float4 a0 = make_float4(0.f, 0.f, 0.f, 0.f);
            float4 a1 = make_float4(0.f, 0.f, 0.f, 0.f);
            const float4* xcol = &s.xh4[g][c4][0];
            const float* kg0 = &s.kg[g][py0 * 8 + pxl][0];
            const float* kg1 = &s.kg[g][(py0 + 1) * 8 + pxl][0];
            #pragma unroll
            for (int rr8 = 0; rr8 < 8; ++rr8) {
                const int row = py0 + rr8;
                float4 xw[7];
                #pragma unroll
                for (int kw = 0; kw < 7; ++kw)
                    xw[kw] = xcol[row * HALO + pxl + kw];
                if (rr8 <= 6) {
                    const float* kgr = kg0 + rr8 * 7;
                    #pragma unroll
                    for (int kw = 0; kw < 7; ++kw) {
                        float kv = kgr[kw];
                        a0.x += kv * xw[kw].x; a0.y += kv * xw[kw].y;
                        a0.z += kv * xw[kw].z; a0.w += kv * xw[kw].w;
                    }
                }
                if (rr8 >= 1) {
                    const float* kgr = kg1 + (rr8 - 1) * 7;
                    #pragma unroll
                    for (int kw = 0; kw < 7; ++kw) {
                        float kv = kgr[kw];
                        a1.x += kv * xw[kw].x; a1.y += kv * xw[kw].y;
                        a1.z += kv * xw[kw].z; a1.w += kv * xw[kw].w;
                    }
                }
            }
            size_t o = (pixbase + (size_t)py0 * WWD + pxl) * CC + (gA + g) * CGC + c4 * 4;
            *(float4*)&out[o] = a0;
            *(float4*)&out[o + (size_t)WWD * CC] = a1;
        }
        __syncthreads();   // protect xh/kg before next iteration overwrites
    }
}

// ------------------------------------------------ launch
extern "C" void kernel_launch(void* const* d_in, const int* in_sizes, int n_in,
                              void* d_out, int out_size) {
    (void)in_sizes; (void)n_in; (void)out_size;
    const float* x        = (const float*)d_in[0];
    const float* w_reduce = (const float*)d_in[1];
    const float* gamma    = (const float*)d_in[2];
    const float* beta     = (const float*)d_in[3];
    const float* mean     = (const float*)d_in[4];
    const float* var      = (const float*)d_in[5];
    const float* w_span   = (const float*)d_in[6];
    const float* b_span   = (const float*)d_in[7];
    float* out = (float*)d_out;

    cudaFuncSetAttribute(rs_kernel, cudaFuncAttributeMaxDynamicSharedMemorySize,
                         (int)sizeof(SmemR));
    cudaFuncSetAttribute(inv_main, cudaFuncAttributeMaxDynamicSharedMemorySize,
                         (int)sizeof(SmemM));

    rs_kernel<<<NRSBLK + 50, 256, sizeof(SmemR)>>>(x, w_reduce, gamma, beta,
                                                   mean, var, w_span);
    dim3 grid(WWD / TILE, HH / TILE, 8);   // (7, 7, 8) = 392 CTAs
    inv_main<<<grid, 256, sizeof(SmemM)>>>(x, b_span, out);
}